// round 11
// baseline (speedup 1.0000x reference)
#include <cuda_runtime.h>
#include <cuda_fp16.h>
#include <cstdint>

// ---------------- problem constants ----------------
#define OC 6
#define LL 3600
#define NROWS 864000
#define NT 256
#define CTILE 256                 // 8 warps x 32 rows
#define NCTILES (NROWS / CTILE)   // 3375

__device__ __forceinline__ uint32_t pack_h2(float a, float b) {
    __half2 h = __floats2half2_rn(a, b);
    return *(uint32_t*)&h;
}

__device__ __forceinline__ void mma16(float c[4], const uint32_t a[4],
                                      uint32_t b0, uint32_t b1) {
    asm volatile(
        "mma.sync.aligned.m16n8k16.row.col.f32.f16.f16.f32 "
        "{%0,%1,%2,%3}, {%4,%5,%6,%7}, {%8,%9}, {%0,%1,%2,%3};"
        : "+f"(c[0]), "+f"(c[1]), "+f"(c[2]), "+f"(c[3])
        : "r"(a[0]), "r"(a[1]), "r"(a[2]), "r"(a[3]), "r"(b0), "r"(b1));
}

__device__ __forceinline__ void cp4(uint32_t dst, const float* g) {
    asm volatile("cp.async.ca.shared.global [%0], [%1], 4;"
                 :: "r"(dst), "l"(g));
}
#define CP_COMMIT() asm volatile("cp.async.commit_group;" ::: "memory")
#define CP_WAIT()   asm volatile("cp.async.wait_all;" ::: "memory")

// Weight B-frag layout: word idx = ((kt*6+ntp)*8+gid)*16 + tig*4 + q.
// afs: warp-private A-frag staging (layer1 -> layer2), thread-local uint4s.
// xst: warp-private gather staging (cp.async prefetch), float2 per (m,lane).
struct SMem {
    uint32_t w1f[4608];
    uint32_t w2f[4608];
    uint32_t w0f[768];
    uint32_t afs[8 * 1536];
    uint32_t xst[8 * 256];
    float2 b0f[48], b1f[48], b2f[48], w3f[48];
    float cs[64];
};
#define SMEM_BYTES ((int)sizeof(SMem))

__global__ void __launch_bounds__(NT, 2)
mlp_cpa_kernel(const float* __restrict__ x, const float* __restrict__ ac,
               const float* __restrict__ W0, const float* __restrict__ b0,
               const float* __restrict__ W1, const float* __restrict__ b1,
               const float* __restrict__ W2, const float* __restrict__ b2,
               const float* __restrict__ W3, const float* __restrict__ b3,
               float* __restrict__ out) {
    extern __shared__ char smraw[];
    SMem& sm = *(SMem*)smraw;
    const int tid  = threadIdx.x;
    const int w    = tid >> 5;
    const int lane = tid & 31;
    const int gid  = lane >> 2;
    const int tig  = lane & 3;

    // ---- stage W1/W2 B-fragments (fp16) ----
    for (int i = tid; i < 4608; i += NT) {
        const int g8 = i >> 4;
        const int sg = g8 & 7;
        const int kp = g8 >> 3;
        const int kt = kp / 6, ntp = kp - kt * 6;
        const int tg = (i >> 2) & 3, q = i & 3;
        const int nt = 2 * ntp + (q >> 1);
        const int k0 = kt * 16 + ((q & 1) ? 8 : 0) + 2 * tg;
        const int n  = nt * 8 + sg;
        const bool okn = (n < 90);
        float v0 = (k0 < 90 && okn) ? W1[k0 * 90 + n] : 0.f;
        float v1 = (k0 + 1 < 90 && okn) ? W1[(k0 + 1) * 90 + n] : 0.f;
        sm.w1f[i] = pack_h2(v0, v1);
        v0 = (k0 < 90 && okn) ? W2[k0 * 90 + n] : 0.f;
        v1 = (k0 + 1 < 90 && okn) ? W2[(k0 + 1) * 90 + n] : 0.f;
        sm.w2f[i] = pack_h2(v0, v1);
    }
    // ---- W0 frags (both k-halves duplicate W0 for hi|lo input split) ----
    for (int i = tid; i < 768; i += NT) {
        const int g8 = i >> 4;
        const int sg = g8 & 7;
        const int ntp = g8 >> 3;
        const int tg = (i >> 2) & 3, q = i & 3;
        const int nt = 2 * ntp + (q >> 1);
        const int n = nt * 8 + sg;
        const int e0 = 2 * tg, e1 = 2 * tg + 1;
        const float v0 = (e0 < 7 && n < 90) ? W0[e0 * 90 + n] : 0.f;
        const float v1 = (e1 < 7 && n < 90) ? W0[e1 * 90 + n] : 0.f;
        sm.w0f[i] = pack_h2(v0, v1);
    }
    if (tid < 48) {
        const int nt = tid >> 2, tg = tid & 3;
        const int n0 = nt * 8 + 2 * tg;
        sm.b0f[tid] = make_float2((n0 < 90) ? b0[n0] : 0.f,
                                  (n0 + 1 < 90) ? b0[n0 + 1] : 0.f);
        sm.b1f[tid] = make_float2((n0 < 90) ? b1[n0] : 0.f,
                                  (n0 + 1 < 90) ? b1[n0 + 1] : 0.f);
        sm.b2f[tid] = make_float2((n0 < 90) ? b2[n0] : 0.f,
                                  (n0 + 1 < 90) ? b2[n0 + 1] : 0.f);
        sm.w3f[tid] = make_float2((n0 < 90) ? W3[n0] : 0.f,
                                  (n0 + 1 < 90) ? W3[n0 + 1] : 0.f);
    }
    if (tid < 60) sm.cs[tid] = ac[tid];
    const float b3v = b3[0];
    __syncthreads();

    const uint32_t* w1base = sm.w1f + gid * 16 + tig * 4;
    const uint32_t* w2base = sm.w2f + gid * 16 + tig * 4;
    const uint32_t* w0base = sm.w0f + gid * 16 + tig * 4;
    uint32_t* afsw = sm.afs + w * 1536 + lane * 4;
    const float2* xstw = (const float2*)(sm.xst + w * 256);
    const uint32_t xstb =
        (uint32_t)__cvta_generic_to_shared(sm.xst + w * 256) + lane * 8;

    // ---- prologue: prefetch first tile's x via cp.async ----
    {
        const int ct0 = blockIdx.x;
        const int Rn = ct0 * CTILE + w * 32;
#pragma unroll
        for (int m = 0; m < 4; m++) {
            const int r = Rn + gid + 8 * m;
            const int g = r / LL, l = r - g * LL;
            const int b = g / 30, rem = g - b * 30;
            const int dev = rem % 5;
            const int i = l / 60, j = l - i * 60;
            const float* xb = x + (b * 64 + i + dev) * 64 + j;
            const uint32_t d = xstb + m * 256;
            if (tig == 0)      { cp4(d, xb + 1); cp4(d + 4, xb + 2); }
            else if (tig == 1) { cp4(d, xb + 3); cp4(d + 4, xb + 4); }
            else if (tig == 2) { cp4(d + 4, xb); }
        }
        CP_COMMIT();
    }

    for (int ct = blockIdx.x; ct < NCTILES; ct += gridDim.x) {
        const int R = ct * CTILE + w * 32;

        // ---- consume prefetched x; build layer-1 A frags (hi/lo split) ----
        CP_WAIT();
        uint32_t A0[2][4];
#pragma unroll
        for (int m = 0; m < 4; m++) {
            const float2 pv = xstw[m * 32 + lane];
            float va = pv.x, vb = pv.y;
            if (tig >= 2) {
                const int r = R + gid + 8 * m;
                const int g = r / LL;
                const int rem = g - (g / 30) * 30;
                va = sm.cs[rem * 2 + (tig - 2)];
                if (tig == 3) vb = 0.f;
            }
            const __half ha = __float2half_rn(va), hb = __float2half_rn(vb);
            const __half2 hh = __halves2half2(ha, hb);
            A0[m >> 1][(m & 1)]     = *(const uint32_t*)&hh;
            A0[m >> 1][(m & 1) + 2] = pack_h2(va - __half2float(ha),
                                              vb - __half2float(hb));
        }

        // ---- prefetch next tile's x (hidden behind all 3 layers) ----
        const int ctn = ct + gridDim.x;
        if (ctn < NCTILES) {
            const int Rn = ctn * CTILE + w * 32;
#pragma unroll
            for (int m = 0; m < 4; m++) {
                const int r = Rn + gid + 8 * m;
                const int g = r / LL, l = r - g * LL;
                const int b = g / 30, rem = g - b * 30;
                const int dev = rem % 5;
                const int i = l / 60, j = l - i * 60;
                const float* xb = x + (b * 64 + i + dev) * 64 + j;
                const uint32_t d = xstb + m * 256;
                if (tig == 0)      { cp4(d, xb + 1); cp4(d + 4, xb + 2); }
                else if (tig == 1) { cp4(d, xb + 3); cp4(d + 4, xb + 4); }
                else if (tig == 2) { cp4(d + 4, xb); }
            }
        }
        CP_COMMIT();

        // ---- layer 1: ntp-outer, store packed A-frags to warp smem ----
#pragma unroll
        for (int ntp = 0; ntp < 6; ntp++) {
            const uint4 bv = *(const uint4*)(w0base + ntp * 128);
            const float2 f0 = sm.b0f[(2 * ntp) * 4 + tig];
            const float2 f1 = sm.b0f[(2 * ntp + 1) * 4 + tig];
#pragma unroll
            for (int mt = 0; mt < 2; mt++) {
                float c0[4] = {f0.x, f0.y, f0.x, f0.y};
                float c1[4] = {f1.x, f1.y, f1.x, f1.y};
                mma16(c0, A0[mt], bv.x, bv.y);
                mma16(c1, A0[mt], bv.z, bv.w);
                uint4 o;
                o.x = pack_h2(fmaxf(c0[0], 0.f), fmaxf(c0[1], 0.f));
                o.y = pack_h2(fmaxf(c0[2], 0.f), fmaxf(c0[3], 0.f));
                o.z = pack_h2(fmaxf(c1[0], 0.f), fmaxf(c1[1], 0.f));
                o.w = pack_h2(fmaxf(c1[2], 0.f), fmaxf(c1[3], 0.f));
                *(uint4*)(afsw + (mt * 6 + ntp) * 128) = o;
            }
        }

        // ---- layer 2: two 48-col halves (48 live accums, reg slack) ----
        uint32_t afB[2][6][4];
#pragma unroll
        for (int h = 0; h < 2; h++) {
            float c[2][6][4];
#pragma unroll
            for (int j = 0; j < 6; j++) {
                const float2 f = sm.b1f[(6 * h + j) * 4 + tig];
#pragma unroll
                for (int mt = 0; mt < 2; mt++) {
                    c[mt][j][0] = f.x; c[mt][j][1] = f.y;
                    c[mt][j][2] = f.x; c[mt][j][3] = f.y;
                }
            }
#pragma unroll
            for (int kt = 0; kt < 6; kt++) {
                const uint4 a0 = *(const uint4*)(afsw + kt * 128);
                const uint4 a1 = *(const uint4*)(afsw + (6 + kt) * 128);
                const uint32_t af0[4] = {a0.x, a0.y, a0.z, a0.w};
                const uint32_t af1[4] = {a1.x, a1.y, a1.z, a1.w};
#pragma unroll
                for (int np = 0; np < 3; np++) {
                    const uint4 bv =
                        *(const uint4*)(w1base + (kt * 6 + 3 * h + np) * 128);
                    mma16(c[0][2 * np],     af0, bv.x, bv.y);
                    mma16(c[0][2 * np + 1], af0, bv.z, bv.w);
                    mma16(c[1][2 * np],     af1, bv.x, bv.y);
                    mma16(c[1][2 * np + 1], af1, bv.z, bv.w);
                }
            }
#pragma unroll
            for (int mt = 0; mt < 2; mt++)
#pragma unroll
                for (int np = 0; np < 3; np++) {
                    const int kt = 3 * h + np;
                    afB[mt][kt][0] = pack_h2(fmaxf(c[mt][2 * np][0], 0.f),
                                             fmaxf(c[mt][2 * np][1], 0.f));
                    afB[mt][kt][1] = pack_h2(fmaxf(c[mt][2 * np][2], 0.f),
                                             fmaxf(c[mt][2 * np][3], 0.f));
                    afB[mt][kt][2] = pack_h2(fmaxf(c[mt][2 * np + 1][0], 0.f),
                                             fmaxf(c[mt][2 * np + 1][1], 0.f));
                    afB[mt][kt][3] = pack_h2(fmaxf(c[mt][2 * np + 1][2], 0.f),
                                             fmaxf(c[mt][2 * np + 1][3], 0.f));
                }
        }

        // ---- layer 3: two 48-col halves + fused 90->1 dot ----
        float s[2][2] = {{0.f, 0.f}, {0.f, 0.f}};
#pragma unroll
        for (int h = 0; h < 2; h++) {
            float ch[2][6][4];
#pragma unroll
            for (int j = 0; j < 6; j++) {
                const float2 f = sm.b2f[(6 * h + j) * 4 + tig];
#pragma unroll
                for (int mt = 0; mt < 2; mt++) {
                    ch[mt][j][0] = f.x; ch[mt][j][1] = f.y;
                    ch[mt][j][2] = f.x; ch[mt][j][3] = f.y;
                }
            }
#pragma unroll
            for (int kt = 0; kt < 6; kt++) {
#pragma unroll
                for (int np = 0; np < 3; np++) {
                    const uint4 bv =
                        *(const uint4*)(w2base + (kt * 6 + 3 * h + np) * 128);
                    mma16(ch[0][2 * np],     afB[0][kt], bv.x, bv.y);
                    mma16(ch[0][2 * np + 1], afB[0][kt], bv.z, bv.w);
                    mma16(ch[1][2 * np],     afB[1][kt], bv.x, bv.y);
                    mma16(ch[1][2 * np + 1], afB[1][kt], bv.z, bv.w);
                }
            }
#pragma unroll
            for (int j = 0; j < 6; j++) {
                const float2 wq = sm.w3f[(6 * h + j) * 4 + tig];
#pragma unroll
                for (int mt = 0; mt < 2; mt++) {
                    s[mt][0] = fmaf(fmaxf(ch[mt][j][0], 0.f), wq.x, s[mt][0]);
                    s[mt][0] = fmaf(fmaxf(ch[mt][j][1], 0.f), wq.y, s[mt][0]);
                    s[mt][1] = fmaf(fmaxf(ch[mt][j][2], 0.f), wq.x, s[mt][1]);
                    s[mt][1] = fmaf(fmaxf(ch[mt][j][3], 0.f), wq.y, s[mt][1]);
                }
            }
        }

        // ---- tig-reduce + atomic out (4 rows per tig==0 thread) ----
#pragma unroll
        for (int mt = 0; mt < 2; mt++) {
#pragma unroll
            for (int hh = 0; hh < 2; hh++) {
                float sv = s[mt][hh];
                sv += __shfl_xor_sync(0xffffffffu, sv, 1);
                sv += __shfl_xor_sync(0xffffffffu, sv, 2);
                if (tig == 0) {
                    const int r = R + gid + 16 * mt + 8 * hh;
                    int g = r / LL, l = r - g * LL;
                    int b = g / 30, rem = g - b * 30;
                    int oc = rem / 5;
                    atomicAdd(out + (b * OC + oc) * LL + l, sv + b3v);
                }
            }
        }
    }
}

__global__ void zero_kernel(float* o, int n) {
    int i = blockIdx.x * blockDim.x + threadIdx.x;
    if (i < n) o[i] = 0.f;
}

extern "C" void kernel_launch(void* const* d_in, const int* in_sizes, int n_in,
                              void* d_out, int out_size) {
    const float* x  = (const float*)d_in[0];
    const float* ac = (const float*)d_in[1];
    const float* W0 = (const float*)d_in[2];
    const float* b0 = (const float*)d_in[3];
    const float* W1 = (const float*)d_in[4];
    const float* b1 = (const float*)d_in[5];
    const float* W2 = (const float*)d_in[6];
    const float* b2 = (const float*)d_in[7];
    const float* W3 = (const float*)d_in[8];
    const float* b3 = (const float*)d_in[9];
    float* out = (float*)d_out;

    int sms = 0;
    cudaDeviceGetAttribute(&sms, cudaDevAttrMultiProcessorCount, 0);
    if (sms <= 0) sms = 148;
    cudaFuncSetAttribute(mlp_cpa_kernel,
                         cudaFuncAttributeMaxDynamicSharedMemorySize, SMEM_BYTES);
    int occ = 1;
    cudaOccupancyMaxActiveBlocksPerMultiprocessor(&occ, mlp_cpa_kernel, NT,
                                                  SMEM_BYTES);
    if (occ < 1) occ = 1;
    int grid = occ * sms;
    if (grid > NCTILES) grid = NCTILES;

    zero_kernel<<<(OC * 8 * LL + 255) / 256, 256>>>(out, OC * 8 * LL);
    mlp_cpa_kernel<<<grid, NT, SMEM_BYTES>>>(x, ac, W0, b0, W1, b1, W2, b2,
                                             W3, b3, out);
}

// round 13
// speedup vs baseline: 1.0205x; 1.0205x over previous
#include <cuda_runtime.h>
#include <cuda_fp16.h>
#include <cstdint>

// ---------------- problem constants ----------------
#define OC 6
#define LL 3600
#define NROWS 864000
#define NT 192
#define CTILE 192                 // 6 warps x 32 rows
#define NCTILES (NROWS / CTILE)   // 4500

__device__ __forceinline__ uint32_t pack_h2(float a, float b) {
    __half2 h = __floats2half2_rn(a, b);
    return *(uint32_t*)&h;
}

__device__ __forceinline__ void mma16(float c[4], const uint32_t a[4],
                                      uint32_t b0, uint32_t b1) {
    asm volatile(
        "mma.sync.aligned.m16n8k16.row.col.f32.f16.f16.f32 "
        "{%0,%1,%2,%3}, {%4,%5,%6,%7}, {%8,%9}, {%0,%1,%2,%3};"
        : "+f"(c[0]), "+f"(c[1]), "+f"(c[2]), "+f"(c[3])
        : "r"(a[0]), "r"(a[1]), "r"(a[2]), "r"(a[3]), "r"(b0), "r"(b1));
}

// Weight B-frag layout: word idx = ((kt*6+ntp)*8+gid)*16 + tig*4 + q
//   q0,q1 = b0,b1 of nt=2ntp ; q2,q3 = b0,b1 of nt=2ntp+1.
// One LDS.128 per (kt,ntp) per thread, conflict-free; serves 4 MMAs (2m x 2n).
// afs: warp-private A-frag staging (layer1 -> layer2), thread-local uint4s,
// no barriers, no conflicts.
struct SMem {
    uint32_t w1f[4608];
    uint32_t w2f[4608];
    uint32_t w0f[768];
    uint32_t afs[6 * 1536];
    float2 b0f[48], b1f[48], b2f[48], w3f[48];
    float cs[64];
};
#define SMEM_BYTES ((int)sizeof(SMem))

__global__ void __launch_bounds__(NT, 2)
mlp_slack_kernel(const float* __restrict__ x, const float* __restrict__ ac,
                 const float* __restrict__ W0, const float* __restrict__ b0,
                 const float* __restrict__ W1, const float* __restrict__ b1,
                 const float* __restrict__ W2, const float* __restrict__ b2,
                 const float* __restrict__ W3, const float* __restrict__ b3,
                 float* __restrict__ out) {
    extern __shared__ char smraw[];
    SMem& sm = *(SMem*)smraw;
    const int tid  = threadIdx.x;
    const int w    = tid >> 5;
    const int lane = tid & 31;
    const int gid  = lane >> 2;
    const int tig  = lane & 3;

    // ---- stage W1/W2 B-fragments (fp16) ----
    for (int i = tid; i < 4608; i += NT) {
        const int g8 = i >> 4;
        const int sg = g8 & 7;
        const int kp = g8 >> 3;            // kt*6+ntp
        const int kt = kp / 6, ntp = kp - kt * 6;
        const int tg = (i >> 2) & 3, q = i & 3;
        const int nt = 2 * ntp + (q >> 1);
        const int k0 = kt * 16 + ((q & 1) ? 8 : 0) + 2 * tg;
        const int n  = nt * 8 + sg;
        const bool okn = (n < 90);
        float v0 = (k0 < 90 && okn) ? W1[k0 * 90 + n] : 0.f;
        float v1 = (k0 + 1 < 90 && okn) ? W1[(k0 + 1) * 90 + n] : 0.f;
        sm.w1f[i] = pack_h2(v0, v1);
        v0 = (k0 < 90 && okn) ? W2[k0 * 90 + n] : 0.f;
        v1 = (k0 + 1 < 90 && okn) ? W2[(k0 + 1) * 90 + n] : 0.f;
        sm.w2f[i] = pack_h2(v0, v1);
    }
    // ---- W0 frags: both k-halves duplicate W0 (hi|lo input split) ----
    for (int i = tid; i < 768; i += NT) {
        const int g8 = i >> 4;
        const int sg = g8 & 7;
        const int ntp = g8 >> 3;           // 0..5
        const int tg = (i >> 2) & 3, q = i & 3;
        const int nt = 2 * ntp + (q >> 1);
        const int n = nt * 8 + sg;
        const int e0 = 2 * tg, e1 = 2 * tg + 1;
        const float v0 = (e0 < 7 && n < 90) ? W0[e0 * 90 + n] : 0.f;
        const float v1 = (e1 < 7 && n < 90) ? W0[e1 * 90 + n] : 0.f;
        sm.w0f[i] = pack_h2(v0, v1);
    }
    if (tid < 48) {
        const int nt = tid >> 2, tg = tid & 3;
        const int n0 = nt * 8 + 2 * tg;
        sm.b0f[tid] = make_float2((n0 < 90) ? b0[n0] : 0.f,
                                  (n0 + 1 < 90) ? b0[n0 + 1] : 0.f);
        sm.b1f[tid] = make_float2((n0 < 90) ? b1[n0] : 0.f,
                                  (n0 + 1 < 90) ? b1[n0 + 1] : 0.f);
        sm.b2f[tid] = make_float2((n0 < 90) ? b2[n0] : 0.f,
                                  (n0 + 1 < 90) ? b2[n0 + 1] : 0.f);
        sm.w3f[tid] = make_float2((n0 < 90) ? W3[n0] : 0.f,
                                  (n0 + 1 < 90) ? W3[n0 + 1] : 0.f);
    }
    if (tid < 60) sm.cs[tid] = ac[tid];
    const float b3v = b3[0];
    __syncthreads();

    const uint32_t* w1base = sm.w1f + gid * 16 + tig * 4;
    const uint32_t* w2base = sm.w2f + gid * 16 + tig * 4;
    const uint32_t* w0base = sm.w0f + gid * 16 + tig * 4;
    uint32_t* afsw = sm.afs + w * 1536 + lane * 4;

    for (int ct = blockIdx.x; ct < NCTILES; ct += gridDim.x) {
        const int R = ct * CTILE + w * 32;

        // ---- layer-1 inputs for 4 row slots, hi/lo fp16 split ----
        uint32_t A0[2][4];
#pragma unroll
        for (int m = 0; m < 4; m++) {
            const int r = R + gid + 8 * m;
            const int g = r / LL, l = r - g * LL;
            const int b = g / 30, rem = g - b * 30;
            const int dev = rem % 5;
            const int i = l / 60, j = l - i * 60;
            const float* xb = x + (b * 64 + i + dev) * 64 + j;
            float va, vb;
            if (tig == 0)      { va = xb[1]; vb = xb[2]; }
            else if (tig == 1) { va = xb[3]; vb = xb[4]; }
            else if (tig == 2) { va = sm.cs[rem * 2]; vb = xb[0]; }
            else               { va = sm.cs[rem * 2 + 1]; vb = 0.f; }
            const __half ha = __float2half_rn(va), hb = __float2half_rn(vb);
            const __half2 hh = __halves2half2(ha, hb);
            A0[m >> 1][(m & 1)]     = *(const uint32_t*)&hh;
            A0[m >> 1][(m & 1) + 2] = pack_h2(va - __half2float(ha),
                                              vb - __half2float(hb));
        }

        // ---- layer 1: ntp-outer, store packed A-frags to warp smem ----
#pragma unroll
        for (int ntp = 0; ntp < 6; ntp++) {
            const uint4 bv = *(const uint4*)(w0base + ntp * 128);
            const float2 f0 = sm.b0f[(2 * ntp) * 4 + tig];
            const float2 f1 = sm.b0f[(2 * ntp + 1) * 4 + tig];
#pragma unroll
            for (int mt = 0; mt < 2; mt++) {
                float c0[4] = {f0.x, f0.y, f0.x, f0.y};
                float c1[4] = {f1.x, f1.y, f1.x, f1.y};
                mma16(c0, A0[mt], bv.x, bv.y);
                mma16(c1, A0[mt], bv.z, bv.w);
                uint4 o;
                o.x = pack_h2(fmaxf(c0[0], 0.f), fmaxf(c0[1], 0.f));
                o.y = pack_h2(fmaxf(c0[2], 0.f), fmaxf(c0[3], 0.f));
                o.z = pack_h2(fmaxf(c1[0], 0.f), fmaxf(c1[1], 0.f));
                o.w = pack_h2(fmaxf(c1[2], 0.f), fmaxf(c1[3], 0.f));
                *(uint4*)(afsw + (mt * 6 + ntp) * 128) = o;
            }
        }

        // ---- layer 2: full width, 24 independent chains, A from smem ----
        float c[2][12][4];
#pragma unroll
        for (int nt = 0; nt < 12; nt++) {
            const float2 f = sm.b1f[nt * 4 + tig];
#pragma unroll
            for (int mt = 0; mt < 2; mt++) {
                c[mt][nt][0] = f.x; c[mt][nt][1] = f.y;
                c[mt][nt][2] = f.x; c[mt][nt][3] = f.y;
            }
        }
#pragma unroll
        for (int kt = 0; kt < 6; kt++) {
            const uint4 a0 = *(const uint4*)(afsw + kt * 128);
            const uint4 a1 = *(const uint4*)(afsw + (6 + kt) * 128);
            const uint32_t af0[4] = {a0.x, a0.y, a0.z, a0.w};
            const uint32_t af1[4] = {a1.x, a1.y, a1.z, a1.w};
#pragma unroll
            for (int ntp = 0; ntp < 6; ntp++) {
                const uint4 bv = *(const uint4*)(w1base + (kt * 6 + ntp) * 128);
                mma16(c[0][2 * ntp],     af0, bv.x, bv.y);
                mma16(c[0][2 * ntp + 1], af0, bv.z, bv.w);
                mma16(c[1][2 * ntp],     af1, bv.x, bv.y);
                mma16(c[1][2 * ntp + 1], af1, bv.z, bv.w);
            }
        }

        // pack layer-2 output into register A-frags (C->A identity)
        uint32_t afB[2][6][4];
#pragma unroll
        for (int mt = 0; mt < 2; mt++)
#pragma unroll
            for (int kt = 0; kt < 6; kt++) {
                afB[mt][kt][0] = pack_h2(fmaxf(c[mt][2 * kt][0], 0.f),
                                         fmaxf(c[mt][2 * kt][1], 0.f));
                afB[mt][kt][1] = pack_h2(fmaxf(c[mt][2 * kt][2], 0.f),
                                         fmaxf(c[mt][2 * kt][3], 0.f));
                afB[mt][kt][2] = pack_h2(fmaxf(c[mt][2 * kt + 1][0], 0.f),
                                         fmaxf(c[mt][2 * kt + 1][1], 0.f));
                afB[mt][kt][3] = pack_h2(fmaxf(c[mt][2 * kt + 1][2], 0.f),
                                         fmaxf(c[mt][2 * kt + 1][3], 0.f));
            }

        // ---- layer 3 in two 48-col halves + fused 90->1 dot ----
        float s[2][2] = {{0.f, 0.f}, {0.f, 0.f}};
#pragma unroll
        for (int h = 0; h < 2; h++) {
            float ch[2][6][4];
#pragma unroll
            for (int j = 0; j < 6; j++) {
                const float2 f = sm.b2f[(6 * h + j) * 4 + tig];
#pragma unroll
                for (int mt = 0; mt < 2; mt++) {
                    ch[mt][j][0] = f.x; ch[mt][j][1] = f.y;
                    ch[mt][j][2] = f.x; ch[mt][j][3] = f.y;
                }
            }
#pragma unroll
            for (int kt = 0; kt < 6; kt++) {
#pragma unroll
                for (int np = 0; np < 3; np++) {
                    const uint4 bv =
                        *(const uint4*)(w2base + (kt * 6 + 3 * h + np) * 128);
                    mma16(ch[0][2 * np],     afB[0][kt], bv.x, bv.y);
                    mma16(ch[0][2 * np + 1], afB[0][kt], bv.z, bv.w);
                    mma16(ch[1][2 * np],     afB[1][kt], bv.x, bv.y);
                    mma16(ch[1][2 * np + 1], afB[1][kt], bv.z, bv.w);
                }
            }
#pragma unroll
            for (int j = 0; j < 6; j++) {
                const float2 wq = sm.w3f[(6 * h + j) * 4 + tig];
#pragma unroll
                for (int mt = 0; mt < 2; mt++) {
                    s[mt][0] = fmaf(fmaxf(ch[mt][j][0], 0.f), wq.x, s[mt][0]);
                    s[mt][0] = fmaf(fmaxf(ch[mt][j][1], 0.f), wq.y, s[mt][0]);
                    s[mt][1] = fmaf(fmaxf(ch[mt][j][2], 0.f), wq.x, s[mt][1]);
                    s[mt][1] = fmaf(fmaxf(ch[mt][j][3], 0.f), wq.y, s[mt][1]);
                }
            }
        }

        // ---- tig-reduce + atomic out (4 rows per tig==0 thread) ----
#pragma unroll
        for (int mt = 0; mt < 2; mt++) {
#pragma unroll
            for (int hh = 0; hh < 2; hh++) {
                float sv = s[mt][hh];
                sv += __shfl_xor_sync(0xffffffffu, sv, 1);
                sv += __shfl_xor_sync(0xffffffffu, sv, 2);
                if (tig == 0) {
                    const int r = R + gid + 16 * mt + 8 * hh;
                    int g = r / LL, l = r - g * LL;
                    int b = g / 30, rem = g - b * 30;
                    int oc = rem / 5;
                    atomicAdd(out + (b * OC + oc) * LL + l, sv + b3v);
                }
            }
        }
    }
}

__global__ void zero_kernel(float* o, int n) {
    int i = blockIdx.x * blockDim.x + threadIdx.x;
    if (i < n) o[i] = 0.f;
}

extern "C" void kernel_launch(void* const* d_in, const int* in_sizes, int n_in,
                              void* d_out, int out_size) {
    const float* x  = (const float*)d_in[0];
    const float* ac = (const float*)d_in[1];
    const float* W0 = (const float*)d_in[2];
    const float* b0 = (const float*)d_in[3];
    const float* W1 = (const float*)d_in[4];
    const float* b1 = (const float*)d_in[5];
    const float* W2 = (const float*)d_in[6];
    const float* b2 = (const float*)d_in[7];
    const float* W3 = (const float*)d_in[8];
    const float* b3 = (const float*)d_in[9];
    float* out = (float*)d_out;

    int sms = 0;
    cudaDeviceGetAttribute(&sms, cudaDevAttrMultiProcessorCount, 0);
    if (sms <= 0) sms = 148;
    cudaFuncSetAttribute(mlp_slack_kernel,
                         cudaFuncAttributeMaxDynamicSharedMemorySize, SMEM_BYTES);
    int occ = 1;
    cudaOccupancyMaxActiveBlocksPerMultiprocessor(&occ, mlp_slack_kernel, NT,
                                                  SMEM_BYTES);
    if (occ < 1) occ = 1;
    int grid = occ * sms;
    if (grid > NCTILES) grid = NCTILES;

    zero_kernel<<<(OC * 8 * LL + 255) / 256, 256>>>(out, OC * 8 * LL);
    mlp_slack_kernel<<<grid, NT, SMEM_BYTES>>>(x, ac, W0, b0, W1, b1, W2, b2,
                                               W3, b3, out);
}

// round 16
// speedup vs baseline: 1.0747x; 1.0531x over previous
#include <cuda_runtime.h>
#include <cuda_fp16.h>
#include <cstdint>

// ---------------- problem constants ----------------
#define OC 6
#define LL 3600
#define NROWS 864000
#define NT 256
#define CTILE 256                 // 8 warps x 32 rows
#define NCTILES (NROWS / CTILE)   // 3375

__device__ __forceinline__ uint32_t pack_h2(float a, float b) {
    __half2 h = __floats2half2_rn(a, b);
    return *(uint32_t*)&h;
}

// f32-accum MMA (layer 1 only)
__device__ __forceinline__ void mma16(float c[4], const uint32_t a[4],
                                      uint32_t b0, uint32_t b1) {
    asm volatile(
        "mma.sync.aligned.m16n8k16.row.col.f32.f16.f16.f32 "
        "{%0,%1,%2,%3}, {%4,%5,%6,%7}, {%8,%9}, {%0,%1,%2,%3};"
        : "+f"(c[0]), "+f"(c[1]), "+f"(c[2]), "+f"(c[3])
        : "r"(a[0]), "r"(a[1]), "r"(a[2]), "r"(a[3]), "r"(b0), "r"(b1));
}

// f16-accum MMA (layers 2 & 3): D reg0 = next-layer a0, reg1 = a1 (identity)
__device__ __forceinline__ void mma16h(uint32_t c[2], const uint32_t a[4],
                                       uint32_t b0, uint32_t b1) {
    asm volatile(
        "mma.sync.aligned.m16n8k16.row.col.f16.f16.f16.f16 "
        "{%0,%1}, {%2,%3,%4,%5}, {%6,%7}, {%0,%1};"
        : "+r"(c[0]), "+r"(c[1])
        : "r"(a[0]), "r"(a[1]), "r"(a[2]), "r"(a[3]), "r"(b0), "r"(b1));
}

__device__ __forceinline__ uint32_t relu2(uint32_t v) {
    __half2 h = *(__half2*)&v;
    h = __hmax2(h, __half2half2(__ushort_as_half((unsigned short)0)));
    return *(uint32_t*)&h;
}

// Weight B-frag layout: word idx = ((kt*6+ntp)*8+gid)*16 + tig*4 + q.
// afs: warp-private A-frag staging (layer1 -> layer2), thread-local uint4s.
struct SMem {
    uint32_t w1f[4608];
    uint32_t w2f[4608];
    uint32_t w0f[768];
    uint32_t afs[8 * 1536];
    float2 b0f[48];
    uint32_t b1h[48], b2h[48];    // packed half2 biases
    float2 w3f[48];
    float cs[64];
};
#define SMEM_BYTES ((int)sizeof(SMem))

__global__ void __launch_bounds__(NT, 2)
mlp_h16_kernel(const float* __restrict__ x, const float* __restrict__ ac,
               const float* __restrict__ W0, const float* __restrict__ b0,
               const float* __restrict__ W1, const float* __restrict__ b1,
               const float* __restrict__ W2, const float* __restrict__ b2,
               const float* __restrict__ W3, const float* __restrict__ b3,
               float* __restrict__ out) {
    extern __shared__ char smraw[];
    SMem& sm = *(SMem*)smraw;
    const int tid  = threadIdx.x;
    const int w    = tid >> 5;
    const int lane = tid & 31;
    const int gid  = lane >> 2;
    const int tig  = lane & 3;

    // ---- stage W1/W2 B-fragments (fp16) ----
    for (int i = tid; i < 4608; i += NT) {
        const int g8 = i >> 4;
        const int sg = g8 & 7;
        const int kp = g8 >> 3;
        const int kt = kp / 6, ntp = kp - kt * 6;
        const int tg = (i >> 2) & 3, q = i & 3;
        const int nt = 2 * ntp + (q >> 1);
        const int k0 = kt * 16 + ((q & 1) ? 8 : 0) + 2 * tg;
        const int n  = nt * 8 + sg;
        const bool okn = (n < 90);
        float v0 = (k0 < 90 && okn) ? W1[k0 * 90 + n] : 0.f;
        float v1 = (k0 + 1 < 90 && okn) ? W1[(k0 + 1) * 90 + n] : 0.f;
        sm.w1f[i] = pack_h2(v0, v1);
        v0 = (k0 < 90 && okn) ? W2[k0 * 90 + n] : 0.f;
        v1 = (k0 + 1 < 90 && okn) ? W2[(k0 + 1) * 90 + n] : 0.f;
        sm.w2f[i] = pack_h2(v0, v1);
    }
    // ---- W0 frags (both k-halves duplicate W0 for hi|lo input split) ----
    for (int i = tid; i < 768; i += NT) {
        const int g8 = i >> 4;
        const int sg = g8 & 7;
        const int ntp = g8 >> 3;
        const int tg = (i >> 2) & 3, q = i & 3;
        const int nt = 2 * ntp + (q >> 1);
        const int n = nt * 8 + sg;
        const int e0 = 2 * tg, e1 = 2 * tg + 1;
        const float v0 = (e0 < 7 && n < 90) ? W0[e0 * 90 + n] : 0.f;
        const float v1 = (e1 < 7 && n < 90) ? W0[e1 * 90 + n] : 0.f;
        sm.w0f[i] = pack_h2(v0, v1);
    }
    if (tid < 48) {
        const int nt = tid >> 2, tg = tid & 3;
        const int n0 = nt * 8 + 2 * tg;
        const float u0 = (n0 < 90), u1 = (n0 + 1 < 90);
        sm.b0f[tid] = make_float2(u0 ? b0[n0] : 0.f, u1 ? b0[n0 + 1] : 0.f);
        sm.b1h[tid] = pack_h2(u0 ? b1[n0] : 0.f, u1 ? b1[n0 + 1] : 0.f);
        sm.b2h[tid] = pack_h2(u0 ? b2[n0] : 0.f, u1 ? b2[n0 + 1] : 0.f);
        sm.w3f[tid] = make_float2(u0 ? W3[n0] : 0.f, u1 ? W3[n0 + 1] : 0.f);
    }
    if (tid < 60) sm.cs[tid] = ac[tid];
    const float b3v = b3[0];
    __syncthreads();

    const uint32_t* w1base = sm.w1f + gid * 16 + tig * 4;
    const uint32_t* w2base = sm.w2f + gid * 16 + tig * 4;
    const uint32_t* w0base = sm.w0f + gid * 16 + tig * 4;
    uint32_t* afsw = sm.afs + w * 1536 + lane * 4;

    for (int ct = blockIdx.x; ct < NCTILES; ct += gridDim.x) {
        const int R = ct * CTILE + w * 32;

        // ---- layer-1 inputs for 4 row slots, hi/lo fp16 split ----
        uint32_t A0[2][4];
#pragma unroll
        for (int m = 0; m < 4; m++) {
            const int r = R + gid + 8 * m;
            const int g = r / LL, l = r - g * LL;
            const int b = g / 30, rem = g - b * 30;
            const int dev = rem % 5;
            const int i = l / 60, j = l - i * 60;
            const float* xb = x + (b * 64 + i + dev) * 64 + j;
            float va, vb;
            if (tig == 0)      { va = xb[1]; vb = xb[2]; }
            else if (tig == 1) { va = xb[3]; vb = xb[4]; }
            else if (tig == 2) { va = sm.cs[rem * 2]; vb = xb[0]; }
            else               { va = sm.cs[rem * 2 + 1]; vb = 0.f; }
            const __half ha = __float2half_rn(va), hb = __float2half_rn(vb);
            const __half2 hh = __halves2half2(ha, hb);
            A0[m >> 1][(m & 1)]     = *(const uint32_t*)&hh;
            A0[m >> 1][(m & 1) + 2] = pack_h2(va - __half2float(ha),
                                              vb - __half2float(hb));
        }

        // ---- layer 1 (f32 accum): ntp-outer, A-frags to warp smem ----
#pragma unroll
        for (int ntp = 0; ntp < 6; ntp++) {
            const uint4 bv = *(const uint4*)(w0base + ntp * 128);
            const float2 f0 = sm.b0f[(2 * ntp) * 4 + tig];
            const float2 f1 = sm.b0f[(2 * ntp + 1) * 4 + tig];
#pragma unroll
            for (int mt = 0; mt < 2; mt++) {
                float c0[4] = {f0.x, f0.y, f0.x, f0.y};
                float c1[4] = {f1.x, f1.y, f1.x, f1.y};
                mma16(c0, A0[mt], bv.x, bv.y);
                mma16(c1, A0[mt], bv.z, bv.w);
                uint4 o;
                o.x = pack_h2(fmaxf(c0[0], 0.f), fmaxf(c0[1], 0.f));
                o.y = pack_h2(fmaxf(c0[2], 0.f), fmaxf(c0[3], 0.f));
                o.z = pack_h2(fmaxf(c1[0], 0.f), fmaxf(c1[1], 0.f));
                o.w = pack_h2(fmaxf(c1[2], 0.f), fmaxf(c1[3], 0.f));
                *(uint4*)(afsw + (mt * 6 + ntp) * 128) = o;
            }
        }

        // ---- layer 2 (f16 accum): full width, 24 indep chains ----
        uint32_t c2[2][12][2];
#pragma unroll
        for (int nt = 0; nt < 12; nt++) {
            const uint32_t bh = sm.b1h[nt * 4 + tig];
#pragma unroll
            for (int mt = 0; mt < 2; mt++) { c2[mt][nt][0] = bh; c2[mt][nt][1] = bh; }
        }
#pragma unroll
        for (int kt = 0; kt < 6; kt++) {
            const uint4 a0 = *(const uint4*)(afsw + kt * 128);
            const uint4 a1 = *(const uint4*)(afsw + (6 + kt) * 128);
            const uint32_t af0[4] = {a0.x, a0.y, a0.z, a0.w};
            const uint32_t af1[4] = {a1.x, a1.y, a1.z, a1.w};
#pragma unroll
            for (int ntp = 0; ntp < 6; ntp++) {
                const uint4 bv = *(const uint4*)(w1base + (kt * 6 + ntp) * 128);
                mma16h(c2[0][2 * ntp],     af0, bv.x, bv.y);
                mma16h(c2[0][2 * ntp + 1], af0, bv.z, bv.w);
                mma16h(c2[1][2 * ntp],     af1, bv.x, bv.y);
                mma16h(c2[1][2 * ntp + 1], af1, bv.z, bv.w);
            }
        }

        // ---- relu: C->A identity (reg0=a0, reg1=a1, next nt pair = a2,a3) ----
        uint32_t afB[2][6][4];
#pragma unroll
        for (int mt = 0; mt < 2; mt++)
#pragma unroll
            for (int kt = 0; kt < 6; kt++) {
                afB[mt][kt][0] = relu2(c2[mt][2 * kt][0]);
                afB[mt][kt][1] = relu2(c2[mt][2 * kt][1]);
                afB[mt][kt][2] = relu2(c2[mt][2 * kt + 1][0]);
                afB[mt][kt][3] = relu2(c2[mt][2 * kt + 1][1]);
            }

        // ---- layer 3 (f16 accum): full width ----
        uint32_t c3[2][12][2];
#pragma unroll
        for (int nt = 0; nt < 12; nt++) {
            const uint32_t bh = sm.b2h[nt * 4 + tig];
#pragma unroll
            for (int mt = 0; mt < 2; mt++) { c3[mt][nt][0] = bh; c3[mt][nt][1] = bh; }
        }
#pragma unroll
        for (int kt = 0; kt < 6; kt++) {
#pragma unroll
            for (int ntp = 0; ntp < 6; ntp++) {
                const uint4 bv = *(const uint4*)(w2base + (kt * 6 + ntp) * 128);
                mma16h(c3[0][2 * ntp],     afB[0][kt], bv.x, bv.y);
                mma16h(c3[0][2 * ntp + 1], afB[0][kt], bv.z, bv.w);
                mma16h(c3[1][2 * ntp],     afB[1][kt], bv.x, bv.y);
                mma16h(c3[1][2 * ntp + 1], afB[1][kt], bv.z, bv.w);
            }
        }

        // ---- fused 90->1 dot (fp32) ----
        float s[2][2] = {{0.f, 0.f}, {0.f, 0.f}};
#pragma unroll
        for (int nt = 0; nt < 12; nt++) {
            const float2 wq = sm.w3f[nt * 4 + tig];
#pragma unroll
            for (int mt = 0; mt < 2; mt++) {
                const float2 lo = __half22float2(*(__half2*)&c3[mt][nt][0]);
                const float2 hi = __half22float2(*(__half2*)&c3[mt][nt][1]);
                s[mt][0] = fmaf(fmaxf(lo.x, 0.f), wq.x, s[mt][0]);
                s[mt][0] = fmaf(fmaxf(lo.y, 0.f), wq.y, s[mt][0]);
                s[mt][1] = fmaf(fmaxf(hi.x, 0.f), wq.x, s[mt][1]);
                s[mt][1] = fmaf(fmaxf(hi.y, 0.f), wq.y, s[mt][1]);
            }
        }

        // ---- tig-reduce + atomic out (4 rows per tig==0 thread) ----
#pragma unroll
        for (int mt = 0; mt < 2; mt++) {
#pragma unroll
            for (int hh = 0; hh < 2; hh++) {
                float sv = s[mt][hh];
                sv += __shfl_xor_sync(0xffffffffu, sv, 1);
                sv += __shfl_xor_sync(0xffffffffu, sv, 2);
                if (tig == 0) {
                    const int r = R + gid + 16 * mt + 8 * hh;
                    int g = r / LL, l = r - g * LL;
                    int b = g / 30, rem = g - b * 30;
                    int oc = rem / 5;
                    atomicAdd(out + (b * OC + oc) * LL + l, sv + b3v);
                }
            }
        }
    }
}

__global__ void zero_kernel(float* o, int n) {
    int i = blockIdx.x * blockDim.x + threadIdx.x;
    if (i < n) o[i] = 0.f;
}

extern "C" void kernel_launch(void* const* d_in, const int* in_sizes, int n_in,
                              void* d_out, int out_size) {
    const float* x  = (const float*)d_in[0];
    const float* ac = (const float*)d_in[1];
    const float* W0 = (const float*)d_in[2];
    const float* b0 = (const float*)d_in[3];
    const float* W1 = (const float*)d_in[4];
    const float* b1 = (const float*)d_in[5];
    const float* W2 = (const float*)d_in[6];
    const float* b2 = (const float*)d_in[7];
    const float* W3 = (const float*)d_in[8];
    const float* b3 = (const float*)d_in[9];
    float* out = (float*)d_out;

    int sms = 0;
    cudaDeviceGetAttribute(&sms, cudaDevAttrMultiProcessorCount, 0);
    if (sms <= 0) sms = 148;
    cudaFuncSetAttribute(mlp_h16_kernel,
                         cudaFuncAttributeMaxDynamicSharedMemorySize, SMEM_BYTES);
    int occ = 1;
    cudaOccupancyMaxActiveBlocksPerMultiprocessor(&occ, mlp_h16_kernel, NT,
                                                  SMEM_BYTES);
    if (occ < 1) occ = 1;
    int grid = occ * sms;
    if (grid > NCTILES) grid = NCTILES;

    zero_kernel<<<(OC * 8 * LL + 255) / 256, 256>>>(out, OC * 8 * LL);
    mlp_h16_kernel<<<grid, NT, SMEM_BYTES>>>(x, ac, W0, b0, W1, b1, W2, b2,
                                             W3, b3, out);
}

// round 17
// speedup vs baseline: 1.0843x; 1.0089x over previous
#include <cuda_runtime.h>
#include <cuda_fp16.h>
#include <cstdint>

// ---------------- problem constants ----------------
#define OC 6
#define LL 3600
#define NROWS 864000
#define NT 256
#define CTILE 256                 // 8 warps x 32 rows
#define NCTILES (NROWS / CTILE)   // 3375

__device__ __forceinline__ uint32_t pack_h2(float a, float b) {
    __half2 h = __floats2half2_rn(a, b);
    return *(uint32_t*)&h;
}

// f32-accum MMA (layer 1 only)
__device__ __forceinline__ void mma16(float c[4], const uint32_t a[4],
                                      uint32_t b0, uint32_t b1) {
    asm volatile(
        "mma.sync.aligned.m16n8k16.row.col.f32.f16.f16.f32 "
        "{%0,%1,%2,%3}, {%4,%5,%6,%7}, {%8,%9}, {%0,%1,%2,%3};"
        : "+f"(c[0]), "+f"(c[1]), "+f"(c[2]), "+f"(c[3])
        : "r"(a[0]), "r"(a[1]), "r"(a[2]), "r"(a[3]), "r"(b0), "r"(b1));
}

// f16-accum MMA (layers 2 & 3): D reg0 = next-layer a0, reg1 = a1 (identity)
__device__ __forceinline__ void mma16h(uint32_t c[2], const uint32_t a[4],
                                       uint32_t b0, uint32_t b1) {
    asm volatile(
        "mma.sync.aligned.m16n8k16.row.col.f16.f16.f16.f16 "
        "{%0,%1}, {%2,%3,%4,%5}, {%6,%7}, {%0,%1};"
        : "+r"(c[0]), "+r"(c[1])
        : "r"(a[0]), "r"(a[1]), "r"(a[2]), "r"(a[3]), "r"(b0), "r"(b1));
}

__device__ __forceinline__ uint32_t relu2(uint32_t v) {
    __half2 h = *(__half2*)&v;
    h = __hmax2(h, __half2half2(__ushort_as_half((unsigned short)0)));
    return *(uint32_t*)&h;
}

// Weight B-frag layout: word idx = ((kt*6+ntp)*8+gid)*16 + tig*4 + q.
struct SMem {
    uint32_t w1f[4608];
    uint32_t w2f[4608];
    uint32_t w0f[768];
    float2 b0f[48];
    uint32_t b1h[48], b2h[48];    // packed half2 biases
    float2 w3f[48];
    float cs[64];
};
#define SMEM_BYTES ((int)sizeof(SMem))

__global__ void __launch_bounds__(NT, 2)
mlp_skew_kernel(const float* __restrict__ x, const float* __restrict__ ac,
                const float* __restrict__ W0, const float* __restrict__ b0,
                const float* __restrict__ W1, const float* __restrict__ b1,
                const float* __restrict__ W2, const float* __restrict__ b2,
                const float* __restrict__ W3, const float* __restrict__ b3,
                float* __restrict__ out) {
    extern __shared__ char smraw[];
    SMem& sm = *(SMem*)smraw;
    const int tid  = threadIdx.x;
    const int w    = tid >> 5;
    const int lane = tid & 31;
    const int gid  = lane >> 2;
    const int tig  = lane & 3;

    // ---- stage W1/W2 B-fragments (fp16) ----
    for (int i = tid; i < 4608; i += NT) {
        const int g8 = i >> 4;
        const int sg = g8 & 7;
        const int kp = g8 >> 3;
        const int kt = kp / 6, ntp = kp - kt * 6;
        const int tg = (i >> 2) & 3, q = i & 3;
        const int nt = 2 * ntp + (q >> 1);
        const int k0 = kt * 16 + ((q & 1) ? 8 : 0) + 2 * tg;
        const int n  = nt * 8 + sg;
        const bool okn = (n < 90);
        float v0 = (k0 < 90 && okn) ? W1[k0 * 90 + n] : 0.f;
        float v1 = (k0 + 1 < 90 && okn) ? W1[(k0 + 1) * 90 + n] : 0.f;
        sm.w1f[i] = pack_h2(v0, v1);
        v0 = (k0 < 90 && okn) ? W2[k0 * 90 + n] : 0.f;
        v1 = (k0 + 1 < 90 && okn) ? W2[(k0 + 1) * 90 + n] : 0.f;
        sm.w2f[i] = pack_h2(v0, v1);
    }
    // ---- W0 frags (both k-halves duplicate W0 for hi|lo input split) ----
    for (int i = tid; i < 768; i += NT) {
        const int g8 = i >> 4;
        const int sg = g8 & 7;
        const int ntp = g8 >> 3;
        const int tg = (i >> 2) & 3, q = i & 3;
        const int nt = 2 * ntp + (q >> 1);
        const int n = nt * 8 + sg;
        const int e0 = 2 * tg, e1 = 2 * tg + 1;
        const float v0 = (e0 < 7 && n < 90) ? W0[e0 * 90 + n] : 0.f;
        const float v1 = (e1 < 7 && n < 90) ? W0[e1 * 90 + n] : 0.f;
        sm.w0f[i] = pack_h2(v0, v1);
    }
    if (tid < 48) {
        const int nt = tid >> 2, tg = tid & 3;
        const int n0 = nt * 8 + 2 * tg;
        const bool u0 = (n0 < 90), u1 = (n0 + 1 < 90);
        sm.b0f[tid] = make_float2(u0 ? b0[n0] : 0.f, u1 ? b0[n0 + 1] : 0.f);
        sm.b1h[tid] = pack_h2(u0 ? b1[n0] : 0.f, u1 ? b1[n0 + 1] : 0.f);
        sm.b2h[tid] = pack_h2(u0 ? b2[n0] : 0.f, u1 ? b2[n0 + 1] : 0.f);
        sm.w3f[tid] = make_float2(u0 ? W3[n0] : 0.f, u1 ? W3[n0 + 1] : 0.f);
    }
    if (tid < 60) sm.cs[tid] = ac[tid];
    const float b3v = b3[0];
    __syncthreads();

    // ---- warp phase-skew: desync the 4 warps sharing each SMSP ----
    {
        const int slot = ((blockIdx.x >= (gridDim.x >> 1)) ? 2 : 0) + (w >> 2);
        const unsigned long long skew = (unsigned long long)slot * 700ull;
        if (skew) {
            const unsigned long long t0 = clock64();
            while (clock64() - t0 < skew) { }
        }
    }

    const uint32_t* w1base = sm.w1f + gid * 16 + tig * 4;
    const uint32_t* w2base = sm.w2f + gid * 16 + tig * 4;
    const uint32_t* w0base = sm.w0f + gid * 16 + tig * 4;

    for (int ct = blockIdx.x; ct < NCTILES; ct += gridDim.x) {
        const int R = ct * CTILE + w * 32;

        // ---- layer-1 inputs for 4 row slots, hi/lo fp16 split ----
        uint32_t A0[2][4];
#pragma unroll
        for (int m = 0; m < 4; m++) {
            const int r = R + gid + 8 * m;
            const int g = r / LL, l = r - g * LL;
            const int b = g / 30, rem = g - b * 30;
            const int dev = rem % 5;
            const int i = l / 60, j = l - i * 60;
            const float* xb = x + (b * 64 + i + dev) * 64 + j;
            float va, vb;
            if (tig == 0)      { va = xb[1]; vb = xb[2]; }
            else if (tig == 1) { va = xb[3]; vb = xb[4]; }
            else if (tig == 2) { va = sm.cs[rem * 2]; vb = xb[0]; }
            else               { va = sm.cs[rem * 2 + 1]; vb = 0.f; }
            const __half ha = __float2half_rn(va), hb = __float2half_rn(vb);
            const __half2 hh = __halves2half2(ha, hb);
            A0[m >> 1][(m & 1)]     = *(const uint32_t*)&hh;
            A0[m >> 1][(m & 1) + 2] = pack_h2(va - __half2float(ha),
                                              vb - __half2float(hb));
        }

        // ---- layer 1 (f32 accum): ntp-outer, A-frags stay in registers ----
        uint32_t afA[2][6][4];
#pragma unroll
        for (int ntp = 0; ntp < 6; ntp++) {
            const uint4 bv = *(const uint4*)(w0base + ntp * 128);
            const float2 f0 = sm.b0f[(2 * ntp) * 4 + tig];
            const float2 f1 = sm.b0f[(2 * ntp + 1) * 4 + tig];
#pragma unroll
            for (int mt = 0; mt < 2; mt++) {
                float c0[4] = {f0.x, f0.y, f0.x, f0.y};
                float c1[4] = {f1.x, f1.y, f1.x, f1.y};
                mma16(c0, A0[mt], bv.x, bv.y);
                mma16(c1, A0[mt], bv.z, bv.w);
                afA[mt][ntp][0] = pack_h2(fmaxf(c0[0], 0.f), fmaxf(c0[1], 0.f));
                afA[mt][ntp][1] = pack_h2(fmaxf(c0[2], 0.f), fmaxf(c0[3], 0.f));
                afA[mt][ntp][2] = pack_h2(fmaxf(c1[0], 0.f), fmaxf(c1[1], 0.f));
                afA[mt][ntp][3] = pack_h2(fmaxf(c1[2], 0.f), fmaxf(c1[3], 0.f));
            }
        }

        // ---- layer 2 (f16 accum): full width, 24 indep chains ----
        uint32_t c2[2][12][2];
#pragma unroll
        for (int nt = 0; nt < 12; nt++) {
            const uint32_t bh = sm.b1h[nt * 4 + tig];
#pragma unroll
            for (int mt = 0; mt < 2; mt++) { c2[mt][nt][0] = bh; c2[mt][nt][1] = bh; }
        }
#pragma unroll
        for (int kt = 0; kt < 6; kt++) {
#pragma unroll
            for (int ntp = 0; ntp < 6; ntp++) {
                const uint4 bv = *(const uint4*)(w1base + (kt * 6 + ntp) * 128);
                mma16h(c2[0][2 * ntp],     afA[0][kt], bv.x, bv.y);
                mma16h(c2[0][2 * ntp + 1], afA[0][kt], bv.z, bv.w);
                mma16h(c2[1][2 * ntp],     afA[1][kt], bv.x, bv.y);
                mma16h(c2[1][2 * ntp + 1], afA[1][kt], bv.z, bv.w);
            }
        }

        // ---- relu: C->A identity (thread-local) ----
        uint32_t afB[2][6][4];
#pragma unroll
        for (int mt = 0; mt < 2; mt++)
#pragma unroll
            for (int kt = 0; kt < 6; kt++) {
                afB[mt][kt][0] = relu2(c2[mt][2 * kt][0]);
                afB[mt][kt][1] = relu2(c2[mt][2 * kt][1]);
                afB[mt][kt][2] = relu2(c2[mt][2 * kt + 1][0]);
                afB[mt][kt][3] = relu2(c2[mt][2 * kt + 1][1]);
            }

        // ---- layer 3 (f16 accum): full width ----
        uint32_t c3[2][12][2];
#pragma unroll
        for (int nt = 0; nt < 12; nt++) {
            const uint32_t bh = sm.b2h[nt * 4 + tig];
#pragma unroll
            for (int mt = 0; mt < 2; mt++) { c3[mt][nt][0] = bh; c3[mt][nt][1] = bh; }
        }
#pragma unroll
        for (int kt = 0; kt < 6; kt++) {
#pragma unroll
            for (int ntp = 0; ntp < 6; ntp++) {
                const uint4 bv = *(const uint4*)(w2base + (kt * 6 + ntp) * 128);
                mma16h(c3[0][2 * ntp],     afB[0][kt], bv.x, bv.y);
                mma16h(c3[0][2 * ntp + 1], afB[0][kt], bv.z, bv.w);
                mma16h(c3[1][2 * ntp],     afB[1][kt], bv.x, bv.y);
                mma16h(c3[1][2 * ntp + 1], afB[1][kt], bv.z, bv.w);
            }
        }

        // ---- fused 90->1 dot (fp32) ----
        float s[2][2] = {{0.f, 0.f}, {0.f, 0.f}};
#pragma unroll
        for (int nt = 0; nt < 12; nt++) {
            const float2 wq = sm.w3f[nt * 4 + tig];
#pragma unroll
            for (int mt = 0; mt < 2; mt++) {
                const float2 lo = __half22float2(*(__half2*)&c3[mt][nt][0]);
                const float2 hi = __half22float2(*(__half2*)&c3[mt][nt][1]);
                s[mt][0] = fmaf(fmaxf(lo.x, 0.f), wq.x, s[mt][0]);
                s[mt][0] = fmaf(fmaxf(lo.y, 0.f), wq.y, s[mt][0]);
                s[mt][1] = fmaf(fmaxf(hi.x, 0.f), wq.x, s[mt][1]);
                s[mt][1] = fmaf(fmaxf(hi.y, 0.f), wq.y, s[mt][1]);
            }
        }

        // ---- tig-reduce + atomic out (4 rows per tig==0 thread) ----
#pragma unroll
        for (int mt = 0; mt < 2; mt++) {
#pragma unroll
            for (int hh = 0; hh < 2; hh++) {
                float sv = s[mt][hh];
                sv += __shfl_xor_sync(0xffffffffu, sv, 1);
                sv += __shfl_xor_sync(0xffffffffu, sv, 2);
                if (tig == 0) {
                    const int r = R + gid + 16 * mt + 8 * hh;
                    int g = r / LL, l = r - g * LL;
                    int b = g / 30, rem = g - b * 30;
                    int oc = rem / 5;
                    atomicAdd(out + (b * OC + oc) * LL + l, sv + b3v);
                }
            }
        }
    }
}

__global__ void zero_kernel(float* o, int n) {
    int i = blockIdx.x * blockDim.x + threadIdx.x;
    if (i < n) o[i] = 0.f;
}

extern "C" void kernel_launch(void* const* d_in, const int* in_sizes, int n_in,
                              void* d_out, int out_size) {
    const float* x  = (const float*)d_in[0];
    const float* ac = (const float*)d_in[1];
    const float* W0 = (const float*)d_in[2];
    const float* b0 = (const float*)d_in[3];
    const float* W1 = (const float*)d_in[4];
    const float* b1 = (const float*)d_in[5];
    const float* W2 = (const float*)d_in[6];
    const float* b2 = (const float*)d_in[7];
    const float* W3 = (const float*)d_in[8];
    const float* b3 = (const float*)d_in[9];
    float* out = (float*)d_out;

    int sms = 0;
    cudaDeviceGetAttribute(&sms, cudaDevAttrMultiProcessorCount, 0);
    if (sms <= 0) sms = 148;
    cudaFuncSetAttribute(mlp_skew_kernel,
                         cudaFuncAttributeMaxDynamicSharedMemorySize, SMEM_BYTES);
    int occ = 1;
    cudaOccupancyMaxActiveBlocksPerMultiprocessor(&occ, mlp_skew_kernel, NT,
                                                  SMEM_BYTES);
    if (occ < 1) occ = 1;
    int grid = occ * sms;
    if (grid > NCTILES) grid = NCTILES;

    zero_kernel<<<(OC * 8 * LL + 255) / 256, 256>>>(out, OC * 8 * LL);
    mlp_skew_kernel<<<grid, NT, SMEM_BYTES>>>(x, ac, W0, b0, W1, b1, W2, b2,
                                              W3, b3, out);
}